// round 16
// baseline (speedup 1.0000x reference)
#include <cuda_runtime.h>
#include <cuda_fp16.h>
#include <math.h>
#include <cstdint>

#define BB 32
#define SS 4096
#define DD 512

// ---------------------------------------------------------------------------
// scratch (no allocation allowed)
// ---------------------------------------------------------------------------
__device__ float g_qadd[BB * DD];           // q@W1 + b1 + b2
__device__ float g_scores[BB * SS];         // logits
__device__ float g_partial[BB * 64 * DD];   // context partials
__device__ float g_msp[BB * 64 * 2];        // per-score-block (max, expsum)
__device__ unsigned short g_w2f[DD * DD];   // fp16 W2, [n][k] k-contiguous

// ---------------------------------------------------------------------------
__device__ __forceinline__ float tanh_fast(float x) {
  float r;
  asm("tanh.approx.f32 %0, %1;" : "=f"(r) : "f"(x));
  return r;
}

__device__ __forceinline__ void mma_f16(float* c, const uint32_t* a, const uint32_t* b) {
  asm volatile(
      "mma.sync.aligned.m16n8k16.row.col.f32.f16.f16.f32 "
      "{%0,%1,%2,%3},{%4,%5,%6,%7},{%8,%9},{%0,%1,%2,%3};"
      : "+f"(c[0]), "+f"(c[1]), "+f"(c[2]), "+f"(c[3])
      : "r"(a[0]), "r"(a[1]), "r"(a[2]), "r"(a[3]), "r"(b[0]), "r"(b[1]));
}

__device__ __forceinline__ void ldsm_x4(uint32_t* r, uint32_t addr) {
  asm volatile("ldmatrix.sync.aligned.m8n8.x4.shared.b16 {%0,%1,%2,%3}, [%4];"
               : "=r"(r[0]), "=r"(r[1]), "=r"(r[2]), "=r"(r[3])
               : "r"(addr));
}

__device__ __forceinline__ void cp16(uint32_t dst, const void* src) {
  asm volatile("cp.async.cg.shared.global [%0], [%1], 16;" :: "r"(dst), "l"(src));
}
#define CP_COMMIT() asm volatile("cp.async.commit_group;" ::: "memory")
#define CP_WAIT1() asm volatile("cp.async.wait_group 1;" ::: "memory")
#define CP_WAIT0() asm volatile("cp.async.wait_group 0;" ::: "memory")

__device__ __forceinline__ uint32_t smem_u32(const void* p) {
  uint32_t a;
  asm("{ .reg .u64 t; cvta.to.shared.u64 t, %1; cvt.u32.u64 %0, t; }" : "=r"(a) : "l"(p));
  return a;
}

// ---------------------------------------------------------------------------
// Kernel 0: fused prep.
//   blocks 0..127   : W2 -> fp16 [n][k] via smem transpose (64k x 32n tiles)
//   blocks 128..383 : qproj (b, 64-col n-chunk, 4-way split-k in-warp)
// ---------------------------------------------------------------------------
__global__ void __launch_bounds__(256) prep_kernel(
    const float* __restrict__ W2, const float* __restrict__ query,
    const float* __restrict__ W1, const float* __restrict__ b1,
    const float* __restrict__ b2) {
  __shared__ float tile[64][36];
  __shared__ float qs[DD];
  int tid = threadIdx.x;
  if (blockIdx.x < 128) {
    int kb = (blockIdx.x & 7) * 64, nb = (blockIdx.x >> 3) * 32;
#pragma unroll
    for (int i = 0; i < 2; i++) {
      int t2 = tid + i * 256;             // 512 = 64 krows * 8 float4
      int r = t2 >> 3, q = t2 & 7;
      float4 v = *(const float4*)(W2 + (size_t)(kb + r) * DD + nb + q * 4);
      *(float4*)&tile[r][q * 4] = v;
    }
    __syncthreads();
    {
      int n = tid >> 3, q = tid & 7;      // 256 = 32 nrows * 8 uint4
      uint32_t h[4];
#pragma unroll
      for (int e = 0; e < 4; e++) {
        __half2 hh = __floats2half2_rn(tile[q * 8 + e * 2 + 0][n],
                                       tile[q * 8 + e * 2 + 1][n]);
        h[e] = *reinterpret_cast<uint32_t*>(&hh);
      }
      size_t off = (size_t)(nb + n) * DD + kb + q * 8;
      *(uint4*)(g_w2f + off) = make_uint4(h[0], h[1], h[2], h[3]);
    }
  } else {
    int j = blockIdx.x - 128;             // 0..255
    int b = j >> 3, qn = j & 7;           // n chunk of 64
    for (int i = tid; i < DD; i += 256) qs[i] = query[b * DD + i];
    __syncthreads();
    int n = qn * 64 + (tid >> 2);
    int k0 = (tid & 3) * 128;
    float acc = 0.f;
#pragma unroll 8
    for (int k = 0; k < 128; k++) acc = fmaf(qs[k0 + k], W1[(k0 + k) * DD + n], acc);
    acc += __shfl_xor_sync(0xffffffffu, acc, 1);
    acc += __shfl_xor_sync(0xffffffffu, acc, 2);
    if (!(tid & 3)) g_qadd[b * DD + n] = acc + b1[n] + b2[n];
  }
}

// ---------------------------------------------------------------------------
// Kernel 2: score GEMM — single fp16 term, 64-row blocks, 2 CTAs/SM so one
// CTA's A fill overlaps the other's MMA. Warp tile 16x64 (4m x 2n warps),
// W2 streamed cp.async 2-stage with 64-k stages. Epilogue emits (max, expsum).
// ---------------------------------------------------------------------------
#define A_STRIDE 1040          // (512+8) fp16 * 2 bytes
#define AH_OFF 0               // 64*1040 = 66560
#define BST_OFF 66560
#define B_RSTRIDE 144          // (64+8) fp16 * 2 bytes
#define B_STAGE 18432          // 128 rows * 144
#define Q_OFF 103424           // 66560 + 2*18432
#define V_OFF 105472
#define P_OFF 107520           // 128 part + 16 red
#define SMEM_TOTAL 108160

__global__ void __launch_bounds__(256, 2) score_mma_kernel(
    const float* __restrict__ values, const float* __restrict__ Vv,
    const float* __restrict__ bv) {
  extern __shared__ char smem[];
  const uint32_t sb = smem_u32(smem);
  const int tid = threadIdx.x;
  const int wid = tid >> 5, lane = tid & 31;
  const int gid = lane >> 2, tig = lane & 3;
  const int wm = wid & 3, wn = wid >> 2;  // 4 m-warps (16 rows) x 2 n-warps (64 cols)
  const int m0 = blockIdx.x * 64;
  const int b = m0 >> 12;

  float* qsh = (float*)(smem + Q_OFF);
  float* vsh = (float*)(smem + V_OFF);
  float* part = (float*)(smem + P_OFF);
  float* red = part + 128;  // 16 floats scratch

  // ---- issue B stage0 for nc=0 first (overlaps A conversion) ----
  {
    uint32_t st = sb + BST_OFF;
#pragma unroll
    for (int i = 0; i < 4; i++) {
      int t2 = tid + i * 256;             // 1024 = 128 rows * 8 uint4
      int r = t2 >> 3, q = t2 & 7;
      cp16(st + r * B_RSTRIDE + q * 16, g_w2f + (size_t)r * DD + q * 8);
    }
    CP_COMMIT();
  }

  // ---- A fill: 64 rows x 512 k -> fp16 plane ----
  for (int task = tid; task < 4096; task += 256) {
    int r = task >> 6, g = task & 63;
    const float4* p4 = (const float4*)(values + (size_t)(m0 + r) * DD + g * 8);
    float4 x0 = p4[0], x1 = p4[1];
    __half2 h0 = __floats2half2_rn(x0.x, x0.y);
    __half2 h1 = __floats2half2_rn(x0.z, x0.w);
    __half2 h2 = __floats2half2_rn(x1.x, x1.y);
    __half2 h3 = __floats2half2_rn(x1.z, x1.w);
    *(uint4*)(smem + AH_OFF + r * A_STRIDE + g * 16) =
        make_uint4(*(uint32_t*)&h0, *(uint32_t*)&h1, *(uint32_t*)&h2, *(uint32_t*)&h3);
  }
  for (int i = tid; i < DD; i += 256) {
    qsh[i] = g_qadd[b * DD + i];
    vsh[i] = Vv[i];
  }

  // ldmatrix per-lane addresses (16x16 A fragment; 64-col B tile per n-warp)
  const int a_row = ((lane >> 3) & 1) * 8 + (lane & 7);
  const int a_col = (lane >> 4) * 16;
  const uint32_t aH_addr = sb + AH_OFF + (wm * 16 + a_row) * A_STRIDE + a_col;
  const int b_row = ((lane >> 4) & 1) * 8 + (lane & 7);
  const int b_col = ((lane >> 3) & 1) * 16;
  const uint32_t b_off = (wn * 64 + b_row) * B_RSTRIDE + b_col;

  float rowsum[2] = {0.f, 0.f};

  for (int nc = 0; nc < 4; ++nc) {
    float acc[8][4];
#pragma unroll
    for (int ni = 0; ni < 8; ni++)
#pragma unroll
      for (int j = 0; j < 4; j++) acc[ni][j] = 0.f;

    const unsigned short* Bg = g_w2f + (size_t)(nc * 128) * DD;

    for (int kt = 0; kt < 8; ++kt) {
      if (kt < 7) {
        uint32_t st = sb + BST_OFF + ((kt + 1) & 1) * B_STAGE;
        const unsigned short* Bk = Bg + (kt + 1) * 64;
#pragma unroll
        for (int i = 0; i < 4; i++) {
          int t2 = tid + i * 256;
          int r = t2 >> 3, q = t2 & 7;
          cp16(st + r * B_RSTRIDE + q * 16, Bk + (size_t)r * DD + q * 8);
        }
        CP_COMMIT();
        CP_WAIT1();
      } else {
        CP_WAIT0();
      }
      __syncthreads();  // stage kt ready (and A ready on first pass)

      const uint32_t stage = sb + BST_OFF + (kt & 1) * B_STAGE;
#pragma unroll
      for (int k16 = 0; k16 < 4; ++k16) {
        int kg = kt * 64 + k16 * 16;
        uint32_t aH[4], bH[4][4];
        ldsm_x4(aH, aH_addr + kg * 2);
        uint32_t bbase = stage + b_off + k16 * 32;
        ldsm_x4(bH[0], bbase);
        ldsm_x4(bH[1], bbase + 16 * B_RSTRIDE);
        ldsm_x4(bH[2], bbase + 32 * B_RSTRIDE);
        ldsm_x4(bH[3], bbase + 48 * B_RSTRIDE);
#pragma unroll
        for (int ni = 0; ni < 8; ni++)
          mma_f16(acc[ni], aH, &bH[ni >> 1][(ni & 1) * 2]);
      }
      __syncthreads();  // all readers done before stage is overwritten
    }

    // prefetch next nc's stage0 (both buffers free now)
    if (nc < 3) {
      uint32_t st = sb + BST_OFF;
      const unsigned short* Bn = g_w2f + (size_t)((nc + 1) * 128) * DD;
#pragma unroll
      for (int i = 0; i < 4; i++) {
        int t2 = tid + i * 256;
        int r = t2 >> 3, q = t2 & 7;
        cp16(st + r * B_RSTRIDE + q * 16, Bn + (size_t)r * DD + q * 8);
      }
      CP_COMMIT();
    }

    // epilogue for this 128-col chunk (tanh.approx: 1 MUFU per element)
#pragma unroll
    for (int ni = 0; ni < 8; ni++)
#pragma unroll
      for (int j = 0; j < 4; j++) {
        int n = nc * 128 + wn * 64 + ni * 8 + tig * 2 + (j & 1);
        float h = tanh_fast(acc[ni][j] + qsh[n]);
        rowsum[j >> 1] = fmaf(h, vsh[n], rowsum[j >> 1]);
      }
  }

#pragma unroll
  for (int i = 0; i < 2; i++) {
    rowsum[i] += __shfl_xor_sync(0xffffffffu, rowsum[i], 1);
    rowsum[i] += __shfl_xor_sync(0xffffffffu, rowsum[i], 2);
  }
  if (tig == 0) {
#pragma unroll
    for (int ri = 0; ri < 2; ri++) {
      int row = wm * 16 + ri * 8 + gid;
      part[wn * 64 + row] = rowsum[ri];
    }
  }
  __syncthreads();
  float sval = -1e30f;
  if (tid < 64) {
    sval = part[tid] + part[64 + tid] + bv[0];
    g_scores[m0 + tid] = sval;
  }

  // ---- per-block (max, expsum) for softmax ----
  float mv = sval;
#pragma unroll
  for (int o = 16; o; o >>= 1) mv = fmaxf(mv, __shfl_xor_sync(0xffffffffu, mv, o));
  __syncthreads();  // part reads complete before red reuse
  if (lane == 0) red[wid] = mv;
  __syncthreads();
  float mloc = red[0];
#pragma unroll
  for (int i = 1; i < 8; i++) mloc = fmaxf(mloc, red[i]);
  float ev = (tid < 64) ? __expf(sval - mloc) : 0.f;
#pragma unroll
  for (int o = 16; o; o >>= 1) ev += __shfl_xor_sync(0xffffffffu, ev, o);
  __syncthreads();
  if (lane == 0) red[8 + wid] = ev;
  __syncthreads();
  if (tid == 0) {
    float v = 0.f;
#pragma unroll
    for (int i = 0; i < 8; i++) v += red[8 + i];
    g_msp[blockIdx.x * 2] = mloc;
    g_msp[blockIdx.x * 2 + 1] = v;
  }
}

// ---------------------------------------------------------------------------
// Kernel 4: context partials, attn written in-flight; inline softmax combine
// of 64 (max, expsum) pairs. Block = (s-chunk of 64, batch); 128 threads.
// ---------------------------------------------------------------------------
#define SCH 64
__global__ void __launch_bounds__(128) ctx_partial_kernel(
    const float* __restrict__ values, float* __restrict__ out) {
  const int t = threadIdx.x;
  const int chunk = blockIdx.x;   // 0..63
  const int b = blockIdx.y;
  const int wrp = t >> 5;
  __shared__ float sM, sInv;
  __shared__ float wredM[4], wredZ[4];
  __shared__ float ps[SS / SCH];

  // combine this batch's 64 (max, expsum) pairs (2 active warps)
  float m = -1e30f, sv = 0.f;
  if (t < 64) {
    m = g_msp[(b * 64 + t) * 2];
    sv = g_msp[(b * 64 + t) * 2 + 1];
  }
  float M = m;
#pragma unroll
  for (int o = 16; o; o >>= 1) M = fmaxf(M, __shfl_xor_sync(0xffffffffu, M, o));
  if ((t & 31) == 0) wredM[wrp] = M;
  __syncthreads();
  float Mg = fmaxf(fmaxf(wredM[0], wredM[1]), fmaxf(wredM[2], wredM[3]));
  float z = sv * __expf(m - Mg);
#pragma unroll
  for (int o = 16; o; o >>= 1) z += __shfl_xor_sync(0xffffffffu, z, o);
  if ((t & 31) == 0) wredZ[wrp] = z;
  __syncthreads();
  if (t == 0) {
    sM = Mg;
    sInv = 1.0f / (((wredZ[0] + wredZ[1]) + wredZ[2]) + wredZ[3]);
  }
  __syncthreads();
  const float mm = sM, inv = sInv;

  const int s0 = chunk * (SS / SCH);
  const float* sc = g_scores + (size_t)b * SS + s0;
  float* attn = out + BB * DD + (size_t)b * SS + s0;
  const float4* vb = (const float4*)(values + ((size_t)b * SS + s0) * DD) + t;

  // probabilities for this chunk (64 values), shared by all threads
  if (t < SS / SCH) {
    float p = __expf(sc[t] - mm) * inv;
    ps[t] = p;
    attn[t] = p;
  }
  __syncthreads();

  float4 acc = make_float4(0.f, 0.f, 0.f, 0.f);
#pragma unroll 8
  for (int s = 0; s < SS / SCH; s++) {
    float p = ps[s];
    float4 v = vb[(size_t)s * (DD / 4)];
    acc.x = fmaf(p, v.x, acc.x);
    acc.y = fmaf(p, v.y, acc.y);
    acc.z = fmaf(p, v.z, acc.z);
    acc.w = fmaf(p, v.w, acc.w);
  }
  *((float4*)(g_partial + ((size_t)(b * SCH + chunk)) * DD) + t) = acc;
}

// ---------------------------------------------------------------------------
// Kernel 5: final reduce — 2 blocks per batch (d-halves), 256 threads;
// thread owns (d4, quarter of 16 partials); fixed-order combine.
// ---------------------------------------------------------------------------
__global__ void __launch_bounds__(256) ctx_reduce_kernel(float* __restrict__ out) {
  const int b = blockIdx.x >> 1;
  const int half = blockIdx.x & 1;
  const int t = threadIdx.x;
  const int d4 = half * 64 + (t & 63);
  const int pq = t >> 6;  // 0..3
  __shared__ float4 sred[256];

  const float4* pp = (const float4*)(g_partial + (size_t)b * SCH * DD) + d4;
  float4 acc = make_float4(0.f, 0.f, 0.f, 0.f);
#pragma unroll 16
  for (int p = pq * 16; p < pq * 16 + 16; p++) {
    float4 v = pp[(size_t)p * (DD / 4)];
    acc.x += v.x;
    acc.y += v.y;
    acc.z += v.z;
    acc.w += v.w;
  }
  sred[t] = acc;
  __syncthreads();
  if (pq == 0) {
    float4 r0 = sred[t];
    float4 r1 = sred[64 + t];
    float4 r2 = sred[128 + t];
    float4 r3 = sred[192 + t];
    float4 r;
    r.x = ((r0.x + r1.x) + r2.x) + r3.x;
    r.y = ((r0.y + r1.y) + r2.y) + r3.y;
    r.z = ((r0.z + r1.z) + r2.z) + r3.z;
    r.w = ((r0.w + r1.w) + r2.w) + r3.w;
    *((float4*)out + b * (DD / 4) + d4) = r;
  }
}

// ---------------------------------------------------------------------------
extern "C" void kernel_launch(void* const* d_in, const int* in_sizes, int n_in,
                              void* d_out, int out_size) {
  const float* query = (const float*)d_in[0];
  const float* values = (const float*)d_in[1];
  const float* W1 = (const float*)d_in[2];
  const float* b1 = (const float*)d_in[3];
  const float* W2 = (const float*)d_in[4];
  const float* b2 = (const float*)d_in[5];
  const float* Vv = (const float*)d_in[6];
  const float* bv = (const float*)d_in[7];
  float* out = (float*)d_out;

  cudaFuncSetAttribute(score_mma_kernel,
                       cudaFuncAttributeMaxDynamicSharedMemorySize, SMEM_TOTAL);

  prep_kernel<<<384, 256>>>(W2, query, W1, b1, b2);
  score_mma_kernel<<<(BB * SS) / 64, 256, SMEM_TOTAL>>>(values, Vv, bv);
  ctx_partial_kernel<<<dim3(SCH, BB), 128>>>(values, out);
  ctx_reduce_kernel<<<BB * 2, 256>>>(out);
}

// round 17
// speedup vs baseline: 1.0317x; 1.0317x over previous
#include <cuda_runtime.h>
#include <cuda_fp16.h>
#include <math.h>
#include <cstdint>

#define BB 32
#define SS 4096
#define DD 512

// ---------------------------------------------------------------------------
// scratch (no allocation allowed)
// ---------------------------------------------------------------------------
__device__ float g_qadd[BB * DD];           // q@W1 + b1 + b2
__device__ float g_scores[BB * SS];         // logits
__device__ float g_partial[BB * 64 * DD];   // context partials
__device__ float g_msp[BB * 32 * 2];        // per-score-block (max, expsum)
__device__ unsigned short g_w2f[DD * DD];   // fp16 W2, [n][k] k-contiguous

// ---------------------------------------------------------------------------
__device__ __forceinline__ float tanh_fast(float x) {
  float r;
  asm("tanh.approx.f32 %0, %1;" : "=f"(r) : "f"(x));
  return r;
}

__device__ __forceinline__ void mma_f16(float* c, const uint32_t* a, const uint32_t* b) {
  asm volatile(
      "mma.sync.aligned.m16n8k16.row.col.f32.f16.f16.f32 "
      "{%0,%1,%2,%3},{%4,%5,%6,%7},{%8,%9},{%0,%1,%2,%3};"
      : "+f"(c[0]), "+f"(c[1]), "+f"(c[2]), "+f"(c[3])
      : "r"(a[0]), "r"(a[1]), "r"(a[2]), "r"(a[3]), "r"(b[0]), "r"(b[1]));
}

__device__ __forceinline__ void ldsm_x4(uint32_t* r, uint32_t addr) {
  asm volatile("ldmatrix.sync.aligned.m8n8.x4.shared.b16 {%0,%1,%2,%3}, [%4];"
               : "=r"(r[0]), "=r"(r[1]), "=r"(r[2]), "=r"(r[3])
               : "r"(addr));
}

__device__ __forceinline__ void cp16(uint32_t dst, const void* src) {
  asm volatile("cp.async.cg.shared.global [%0], [%1], 16;" :: "r"(dst), "l"(src));
}
#define CP_COMMIT() asm volatile("cp.async.commit_group;" ::: "memory")
#define CP_WAIT1() asm volatile("cp.async.wait_group 1;" ::: "memory")
#define CP_WAIT0() asm volatile("cp.async.wait_group 0;" ::: "memory")

__device__ __forceinline__ uint32_t smem_u32(const void* p) {
  uint32_t a;
  asm("{ .reg .u64 t; cvta.to.shared.u64 t, %1; cvt.u32.u64 %0, t; }" : "=r"(a) : "l"(p));
  return a;
}

// ---------------------------------------------------------------------------
// Kernel 0: fused prep.
//   blocks 0..127   : W2 -> fp16 [n][k] via smem transpose (64k x 32n tiles)
//   blocks 128..383 : qproj (b, 64-col n-chunk, 4-way split-k in-warp)
// ---------------------------------------------------------------------------
__global__ void __launch_bounds__(256) prep_kernel(
    const float* __restrict__ W2, const float* __restrict__ query,
    const float* __restrict__ W1, const float* __restrict__ b1,
    const float* __restrict__ b2) {
  __shared__ float tile[64][36];
  __shared__ float qs[DD];
  int tid = threadIdx.x;
  if (blockIdx.x < 128) {
    int kb = (blockIdx.x & 7) * 64, nb = (blockIdx.x >> 3) * 32;
#pragma unroll
    for (int i = 0; i < 2; i++) {
      int t2 = tid + i * 256;             // 512 = 64 krows * 8 float4
      int r = t2 >> 3, q = t2 & 7;
      float4 v = *(const float4*)(W2 + (size_t)(kb + r) * DD + nb + q * 4);
      *(float4*)&tile[r][q * 4] = v;
    }
    __syncthreads();
    {
      int n = tid >> 3, q = tid & 7;      // 256 = 32 nrows * 8 uint4
      uint32_t h[4];
#pragma unroll
      for (int e = 0; e < 4; e++) {
        __half2 hh = __floats2half2_rn(tile[q * 8 + e * 2 + 0][n],
                                       tile[q * 8 + e * 2 + 1][n]);
        h[e] = *reinterpret_cast<uint32_t*>(&hh);
      }
      size_t off = (size_t)(nb + n) * DD + kb + q * 8;
      *(uint4*)(g_w2f + off) = make_uint4(h[0], h[1], h[2], h[3]);
    }
  } else {
    int j = blockIdx.x - 128;             // 0..255
    int b = j >> 3, qn = j & 7;           // n chunk of 64
    for (int i = tid; i < DD; i += 256) qs[i] = query[b * DD + i];
    __syncthreads();
    int n = qn * 64 + (tid >> 2);
    int k0 = (tid & 3) * 128;
    float acc = 0.f;
#pragma unroll 8
    for (int k = 0; k < 128; k++) acc = fmaf(qs[k0 + k], W1[(k0 + k) * DD + n], acc);
    acc += __shfl_xor_sync(0xffffffffu, acc, 1);
    acc += __shfl_xor_sync(0xffffffffu, acc, 2);
    if (!(tid & 3)) g_qadd[b * DD + n] = acc + b1[n] + b2[n];
  }
}

// ---------------------------------------------------------------------------
// Kernel 2: score GEMM — single fp16 term. Block: 128 rows resident,
// warp tile 32x64, W2 streamed cp.async 2-stage with 128-k stages.
// Epilogue also emits per-block (max, expsum) to g_msp.
// ---------------------------------------------------------------------------
#define A_STRIDE 1040          // (512+8) fp16 * 2 bytes
#define AH_OFF 0               // 128*1040 = 133120
#define BST_OFF 133120
#define B_RSTRIDE 272          // (128+8) fp16 * 2 bytes
#define B_STAGE 34816          // 128 rows * 272
#define Q_OFF 202752           // 133120 + 2*34816
#define V_OFF 204800
#define P_OFF 206848           // 256 floats + 16 scratch
#define SMEM_TOTAL 207936

__global__ void __launch_bounds__(256, 1) score_mma_kernel(
    const float* __restrict__ values, const float* __restrict__ Vv,
    const float* __restrict__ bv) {
  extern __shared__ char smem[];
  const uint32_t sb = smem_u32(smem);
  const int tid = threadIdx.x;
  const int wid = tid >> 5, lane = tid & 31;
  const int gid = lane >> 2, tig = lane & 3;
  const int wm = wid & 3, wn = wid >> 2;  // 4 m-warps x 2 n-warps
  const int m0 = blockIdx.x * 128;
  const int b = m0 >> 12;

  float* qsh = (float*)(smem + Q_OFF);
  float* vsh = (float*)(smem + V_OFF);
  float* part = (float*)(smem + P_OFF);
  float* red = part + 256;  // 16 floats scratch

  // ---- issue B stage0 for nc=0 first (overlaps A conversion) ----
  {
    uint32_t st = sb + BST_OFF;
#pragma unroll
    for (int i = 0; i < 8; i++) {
      int t2 = tid + i * 256;
      int r = t2 >> 4, q = t2 & 15;
      cp16(st + r * B_RSTRIDE + q * 16, g_w2f + (size_t)r * DD + q * 8);
    }
    CP_COMMIT();
  }

  // ---- A fill: 128 rows x 512 k -> fp16 plane ----
  for (int task = tid; task < 8192; task += 256) {
    int r = task >> 6, g = task & 63;
    const float4* p4 = (const float4*)(values + (size_t)(m0 + r) * DD + g * 8);
    float4 x0 = p4[0], x1 = p4[1];
    __half2 h0 = __floats2half2_rn(x0.x, x0.y);
    __half2 h1 = __floats2half2_rn(x0.z, x0.w);
    __half2 h2 = __floats2half2_rn(x1.x, x1.y);
    __half2 h3 = __floats2half2_rn(x1.z, x1.w);
    *(uint4*)(smem + AH_OFF + r * A_STRIDE + g * 16) =
        make_uint4(*(uint32_t*)&h0, *(uint32_t*)&h1, *(uint32_t*)&h2, *(uint32_t*)&h3);
  }
  for (int i = tid; i < DD; i += 256) {
    qsh[i] = g_qadd[b * DD + i];
    vsh[i] = Vv[i];
  }

  // ldmatrix per-lane addresses
  const int a_row = ((lane >> 3) & 1) * 8 + (lane & 7);
  const int a_col = (lane >> 4) * 16;
  const uint32_t aH_addr = sb + AH_OFF + (wm * 32 + a_row) * A_STRIDE + a_col;
  const int b_row = ((lane >> 4) & 1) * 8 + (lane & 7);
  const int b_col = ((lane >> 3) & 1) * 16;
  const uint32_t b_off = (wn * 64 + b_row) * B_RSTRIDE + b_col;

  float rowsum[4] = {0.f, 0.f, 0.f, 0.f};

  for (int nc = 0; nc < 4; ++nc) {
    float acc[2][8][4];
#pragma unroll
    for (int mi = 0; mi < 2; mi++)
#pragma unroll
      for (int ni = 0; ni < 8; ni++)
#pragma unroll
        for (int j = 0; j < 4; j++) acc[mi][ni][j] = 0.f;

    const unsigned short* Bg = g_w2f + (size_t)(nc * 128) * DD;

    for (int kt = 0; kt < 4; ++kt) {
      if (kt < 3) {
        uint32_t st = sb + BST_OFF + ((kt + 1) & 1) * B_STAGE;
        const unsigned short* Bk = Bg + (kt + 1) * 128;
#pragma unroll
        for (int i = 0; i < 8; i++) {
          int t2 = tid + i * 256;
          int r = t2 >> 4, q = t2 & 15;
          cp16(st + r * B_RSTRIDE + q * 16, Bk + (size_t)r * DD + q * 8);
        }
        CP_COMMIT();
        CP_WAIT1();
      } else {
        CP_WAIT0();
      }
      __syncthreads();  // stage kt ready (and A ready on first pass)

      const uint32_t stage = sb + BST_OFF + (kt & 1) * B_STAGE;
#pragma unroll
      for (int k16 = 0; k16 < 8; ++k16) {
        int kg = kt * 128 + k16 * 16;
        uint32_t aH[2][4], bH[4][4];
        ldsm_x4(aH[0], aH_addr + kg * 2);
        ldsm_x4(aH[1], aH_addr + 16 * A_STRIDE + kg * 2);
        uint32_t bbase = stage + b_off + k16 * 32;
        ldsm_x4(bH[0], bbase);
        ldsm_x4(bH[1], bbase + 16 * B_RSTRIDE);
        ldsm_x4(bH[2], bbase + 32 * B_RSTRIDE);
        ldsm_x4(bH[3], bbase + 48 * B_RSTRIDE);
#pragma unroll
        for (int mi = 0; mi < 2; mi++)
#pragma unroll
          for (int ni = 0; ni < 8; ni++)
            mma_f16(acc[mi][ni], aH[mi], &bH[ni >> 1][(ni & 1) * 2]);
      }
      __syncthreads();  // all readers done before stage is overwritten
    }

    // prefetch next nc's stage0 (both buffers free now)
    if (nc < 3) {
      uint32_t st = sb + BST_OFF;
      const unsigned short* Bn = g_w2f + (size_t)((nc + 1) * 128) * DD;
#pragma unroll
      for (int i = 0; i < 8; i++) {
        int t2 = tid + i * 256;
        int r = t2 >> 4, q = t2 & 15;
        cp16(st + r * B_RSTRIDE + q * 16, Bn + (size_t)r * DD + q * 8);
      }
      CP_COMMIT();
    }

    // epilogue for this 128-col chunk (tanh.approx: 1 MUFU per element)
#pragma unroll
    for (int mi = 0; mi < 2; mi++)
#pragma unroll
      for (int ni = 0; ni < 8; ni++)
#pragma unroll
        for (int j = 0; j < 4; j++) {
          int n = nc * 128 + wn * 64 + ni * 8 + tig * 2 + (j & 1);
          float h = tanh_fast(acc[mi][ni][j] + qsh[n]);
          rowsum[mi * 2 + (j >> 1)] = fmaf(h, vsh[n], rowsum[mi * 2 + (j >> 1)]);
        }
  }

#pragma unroll
  for (int i = 0; i < 4; i++) {
    rowsum[i] += __shfl_xor_sync(0xffffffffu, rowsum[i], 1);
    rowsum[i] += __shfl_xor_sync(0xffffffffu, rowsum[i], 2);
  }
  if (tig == 0) {
#pragma unroll
    for (int mi = 0; mi < 2; mi++)
#pragma unroll
      for (int ri = 0; ri < 2; ri++) {
        int row = wm * 32 + mi * 16 + ri * 8 + gid;
        part[wn * 128 + row] = rowsum[mi * 2 + ri];
      }
  }
  __syncthreads();
  float sval = -1e30f;
  if (tid < 128) {
    sval = part[tid] + part[128 + tid] + bv[0];
    g_scores[m0 + tid] = sval;
  }

  // ---- per-block (max, expsum) for softmax ----
  float mv = sval;
#pragma unroll
  for (int o = 16; o; o >>= 1) mv = fmaxf(mv, __shfl_xor_sync(0xffffffffu, mv, o));
  __syncthreads();  // part reads complete before red reuse
  if (lane == 0) red[wid] = mv;
  __syncthreads();
  float mloc = red[0];
#pragma unroll
  for (int i = 1; i < 8; i++) mloc = fmaxf(mloc, red[i]);
  float ev = (tid < 128) ? __expf(sval - mloc) : 0.f;
#pragma unroll
  for (int o = 16; o; o >>= 1) ev += __shfl_xor_sync(0xffffffffu, ev, o);
  __syncthreads();
  if (lane == 0) red[8 + wid] = ev;
  __syncthreads();
  if (tid == 0) {
    float v = 0.f;
#pragma unroll
    for (int i = 0; i < 8; i++) v += red[8 + i];
    g_msp[blockIdx.x * 2] = mloc;
    g_msp[blockIdx.x * 2 + 1] = v;
  }
}

// ---------------------------------------------------------------------------
// Kernel 4: context partials, attn written in-flight; inline softmax combine.
// Block = (s-chunk of 64, batch); 128 threads x float4 (coalesced 2KB/row).
// Two independent accumulators (even/odd s) double in-flight loads.
// ---------------------------------------------------------------------------
#define SCH 64
__global__ void __launch_bounds__(128) ctx_partial_kernel(
    const float* __restrict__ values, float* __restrict__ out) {
  const int t = threadIdx.x;
  const int chunk = blockIdx.x;   // 0..63
  const int b = blockIdx.y;
  __shared__ float sM, sInv;
  __shared__ float ps[SS / SCH];

  // combine this batch's 32 (max, expsum) pairs
  if (t < 32) {
    float m = g_msp[(b * 32 + t) * 2];
    float sv = g_msp[(b * 32 + t) * 2 + 1];
    float M = m;
#pragma unroll
    for (int o = 16; o; o >>= 1) M = fmaxf(M, __shfl_xor_sync(0xffffffffu, M, o));
    float z = sv * __expf(m - M);
#pragma unroll
    for (int o = 16; o; o >>= 1) z += __shfl_xor_sync(0xffffffffu, z, o);
    if (t == 0) {
      sM = M;
      sInv = 1.0f / z;
    }
  }
  __syncthreads();
  const float m = sM, inv = sInv;

  const int s0 = chunk * (SS / SCH);
  const float* sc = g_scores + (size_t)b * SS + s0;
  float* attn = out + BB * DD + (size_t)b * SS + s0;
  const float4* vb = (const float4*)(values + ((size_t)b * SS + s0) * DD) + t;

  // probabilities for this chunk (64 values), shared by all threads
  if (t < SS / SCH) {
    float p = __expf(sc[t] - m) * inv;
    ps[t] = p;
    attn[t] = p;
  }
  __syncthreads();

  float4 acc0 = make_float4(0.f, 0.f, 0.f, 0.f);
  float4 acc1 = make_float4(0.f, 0.f, 0.f, 0.f);
#pragma unroll 8
  for (int s = 0; s < SS / SCH; s += 2) {
    float p0 = ps[s];
    float p1 = ps[s + 1];
    float4 v0 = vb[(size_t)s * (DD / 4)];
    float4 v1 = vb[(size_t)(s + 1) * (DD / 4)];
    acc0.x = fmaf(p0, v0.x, acc0.x);
    acc0.y = fmaf(p0, v0.y, acc0.y);
    acc0.z = fmaf(p0, v0.z, acc0.z);
    acc0.w = fmaf(p0, v0.w, acc0.w);
    acc1.x = fmaf(p1, v1.x, acc1.x);
    acc1.y = fmaf(p1, v1.y, acc1.y);
    acc1.z = fmaf(p1, v1.z, acc1.z);
    acc1.w = fmaf(p1, v1.w, acc1.w);
  }
  float4 acc;
  acc.x = acc0.x + acc1.x;
  acc.y = acc0.y + acc1.y;
  acc.z = acc0.z + acc1.z;
  acc.w = acc0.w + acc1.w;
  *((float4*)(g_partial + ((size_t)(b * SCH + chunk)) * DD) + t) = acc;
}

// ---------------------------------------------------------------------------
// Kernel 5: final reduce — one block per batch, 512 threads; thread owns
// (d4 = t&127, quarter = t>>7 of 16 partials); quarters combined via SMEM in
// fixed order (deterministic across replays).
// ---------------------------------------------------------------------------
__global__ void __launch_bounds__(512) ctx_reduce_kernel(float* __restrict__ out) {
  const int b = blockIdx.x;
  const int t = threadIdx.x;
  const int d4 = t & 127;
  const int pq = t >> 7;  // 0..3
  __shared__ float4 sred[512];

  const float4* pp = (const float4*)(g_partial + (size_t)b * SCH * DD) + d4;
  float4 acc = make_float4(0.f, 0.f, 0.f, 0.f);
#pragma unroll 16
  for (int p = pq * 16; p < pq * 16 + 16; p++) {
    float4 v = pp[(size_t)p * (DD / 4)];
    acc.x += v.x;
    acc.y += v.y;
    acc.z += v.z;
    acc.w += v.w;
  }
  sred[t] = acc;
  __syncthreads();
  if (pq == 0) {
    float4 r0 = sred[d4];
    float4 r1 = sred[128 + d4];
    float4 r2 = sred[256 + d4];
    float4 r3 = sred[384 + d4];
    float4 r;
    r.x = ((r0.x + r1.x) + r2.x) + r3.x;
    r.y = ((r0.y + r1.y) + r2.y) + r3.y;
    r.z = ((r0.z + r1.z) + r2.z) + r3.z;
    r.w = ((r0.w + r1.w) + r2.w) + r3.w;
    *((float4*)out + b * (DD / 4) + d4) = r;
  }
}

// ---------------------------------------------------------------------------
extern "C" void kernel_launch(void* const* d_in, const int* in_sizes, int n_in,
                              void* d_out, int out_size) {
  const float* query = (const float*)d_in[0];
  const float* values = (const float*)d_in[1];
  const float* W1 = (const float*)d_in[2];
  const float* b1 = (const float*)d_in[3];
  const float* W2 = (const float*)d_in[4];
  const float* b2 = (const float*)d_in[5];
  const float* Vv = (const float*)d_in[6];
  const float* bv = (const float*)d_in[7];
  float* out = (float*)d_out;

  cudaFuncSetAttribute(score_mma_kernel,
                       cudaFuncAttributeMaxDynamicSharedMemorySize, SMEM_TOTAL);

  prep_kernel<<<384, 256>>>(W2, query, W1, b1, b2);
  score_mma_kernel<<<(BB * SS) / 128, 256, SMEM_TOTAL>>>(values, Vv, bv);
  ctx_partial_kernel<<<dim3(SCH, BB), 128>>>(values, out);
  ctx_reduce_kernel<<<BB, 512>>>(out);
}